// round 2
// baseline (speedup 1.0000x reference)
#include <cuda_runtime.h>
#include <cuda_fp16.h>
#include <math.h>

// Problem constants
#define HWC 16384                 // H*W = 128*128
#define HWS ((size_t)HWC)
#define NB 8                      // batch
#define PERN ((size_t)256*HWS)    // elements per n for 256-ch tensors (4194304)

// ---------------------------------------------------------------------------
// Scratch (device globals; no allocation allowed)
// ---------------------------------------------------------------------------
__device__ __align__(256) float g_y[(size_t)NB * 512 * HWC];    // proj out, reused as MLP hidden (256MB)
__device__ __align__(256) float g_nx[(size_t)NB * 256 * HWC];   // cluster output (128MB)
__device__ __align__(256) float g_newx[(size_t)NB * 256 * HWC]; // merge out -> normalized (128MB)
__device__ __align__(256) float g_t[(size_t)NB * 256 * HWC];    // mlp out (128MB)
__device__ double g_psum[2][NB][64];
__device__ double g_psq[2][NB][64];
__device__ float  g_stat[2][NB][2];   // mu, rstd

// ---------------------------------------------------------------------------
// Tiled FP32 GEMM: C[n] (MM x HWC) = A (MM x KK) * B[n] (KK x HWC) + bias
// BM=BN=128, BK=8, 256 threads, 8x8 per thread (2x2 quads of float4).
// AT:    A is stored (KK x MM) row-major (transposed access: A[k][m])
// BSRC:  0 = Bx (x input, KK rows per n)
//        1 = g_nx
//        2 = concat(Bx rows 0..255, g_newx rows 256..511)
//        3 = g_y (512 rows per n)
// CSEL:  0 = g_y, 1 = g_newx, 2 = g_t
// ---------------------------------------------------------------------------
template<int KK, int MM, bool AT, bool GELU, int BSRC, int CSEL>
__global__ void __launch_bounds__(256)
sgemm_kernel(const float* __restrict__ A, const float* __restrict__ Bx,
             const float* __restrict__ bias)
{
    __shared__ float As[8][128];
    __shared__ float Bs[8][128];

    const int tid = threadIdx.x;
    const int tx = tid & 15;
    const int ty = tid >> 4;
    const int n    = blockIdx.z;
    const int row0 = blockIdx.y * 128;
    const int col0 = blockIdx.x * 128;

    float acc[8][8];
#pragma unroll
    for (int i = 0; i < 8; i++)
#pragma unroll
        for (int j = 0; j < 8; j++) acc[i][j] = 0.f;

    for (int kt = 0; kt < KK / 8; ++kt) {
        __syncthreads();
        // ---- load A tile into As[k][m]
        if (AT) {
#pragma unroll
            for (int i = 0; i < 4; i++) {
                int idx = tid + i * 256;
                int kk = idx >> 7, mm = idx & 127;
                As[kk][mm] = A[(size_t)(kt * 8 + kk) * MM + row0 + mm];
            }
        } else {
#pragma unroll
            for (int i = 0; i < 4; i++) {
                int idx = tid + i * 256;
                int mm = idx >> 3, kk = idx & 7;
                As[kk][mm] = A[(size_t)(row0 + mm) * KK + kt * 8 + kk];
            }
        }
        // ---- load B tile (each thread: one float4)
        {
            int kk = tid >> 5;
            int c4 = (tid & 31) * 4;
            int krow = kt * 8 + kk;
            const float* br;
            if (BSRC == 0)      br = Bx     + ((size_t)n * KK + krow) * HWS;
            else if (BSRC == 1) br = g_nx   + ((size_t)n * 256 + krow) * HWS;
            else if (BSRC == 2) br = (krow < 256)
                                   ? (Bx     + ((size_t)n * 256 + krow) * HWS)
                                   : (g_newx + ((size_t)n * 256 + (krow - 256)) * HWS);
            else                br = g_y    + ((size_t)n * 512 + krow) * HWS;
            float4 v = *reinterpret_cast<const float4*>(br + col0 + c4);
            *reinterpret_cast<float4*>(&Bs[kk][c4]) = v;
        }
        __syncthreads();
        // ---- compute
#pragma unroll
        for (int kk = 0; kk < 8; kk++) {
            float4 a0 = *reinterpret_cast<const float4*>(&As[kk][ty * 4]);
            float4 a1 = *reinterpret_cast<const float4*>(&As[kk][64 + ty * 4]);
            float4 b0 = *reinterpret_cast<const float4*>(&Bs[kk][tx * 4]);
            float4 b1 = *reinterpret_cast<const float4*>(&Bs[kk][64 + tx * 4]);
            float aa[8] = {a0.x, a0.y, a0.z, a0.w, a1.x, a1.y, a1.z, a1.w};
            float bb[8] = {b0.x, b0.y, b0.z, b0.w, b1.x, b1.y, b1.z, b1.w};
#pragma unroll
            for (int i = 0; i < 8; i++)
#pragma unroll
                for (int j = 0; j < 8; j++)
                    acc[i][j] = fmaf(aa[i], bb[j], acc[i][j]);
        }
    }

    float* C = (CSEL == 0) ? g_y : (CSEL == 1) ? g_newx : g_t;
#pragma unroll
    for (int i = 0; i < 8; i++) {
        int r = row0 + ((i < 4) ? (ty * 4 + i) : (64 + ty * 4 + (i - 4)));
        float bv = bias[r];
        float v[8];
#pragma unroll
        for (int j = 0; j < 8; j++) {
            float u = acc[i][j] + bv;
            if (GELU) u = u * normcdff(u);   // exact gelu: x * Phi(x)
            v[j] = u;
        }
        size_t cb = ((size_t)n * MM + r) * HWS;
        *reinterpret_cast<float4*>(&C[cb + col0 + tx * 4])      = make_float4(v[0], v[1], v[2], v[3]);
        *reinterpret_cast<float4*>(&C[cb + col0 + 64 + tx * 4]) = make_float4(v[4], v[5], v[6], v[7]);
    }
}

// ---------------------------------------------------------------------------
// Fused local-cluster kernel: one block per m-tile (m = 256)
// Reads g_y, writes g_nx. Phases: centers -> normalize centers -> sim/argmax
// + scatter (smem atomics) -> cluster normalize -> gather/write.
// ---------------------------------------------------------------------------
__global__ void __launch_bounds__(256)
cluster_kernel(const float* __restrict__ alpha_p, const float* __restrict__ beta_p)
{
    __shared__ float sc[64][64];          // centers [c][s]
    __shared__ float cpn[64][33];         // normalized point centers [s][j], reused as ncn
    __shared__ __half svals[4096];
    __shared__ unsigned char sidx[4096];
    __shared__ float ncs[64][33];         // cluster accumulators

    const int tid = threadIdx.x;
    const int m = blockIdx.x;
    const int n   = m >> 5;
    const int f   = (m >> 2) & 7;
    const int fs1 = (m >> 1) & 1;
    const int fs2 = m & 1;
    const int roff = fs1 * 64, coff = fs2 * 64;
    const size_t ybase = ((size_t)n * 512 + (size_t)f * 64) * HWS;

    const float al = alpha_p[0];
    const float be = beta_p[0];

    // ---- Phase 1: centers (8x8 pooling). 4096 (c,s) pairs, 16 per thread.
#pragma unroll 1
    for (int i = 0; i < 16; i++) {
        int pi = i * 256 + tid;
        int c = pi >> 6, s = pi & 63;
        int a = s >> 3, b = s & 7;
        const float* p = g_y + ybase + (size_t)c * HWS + (size_t)(roff + a * 8) * 128 + coff + b * 8;
        float sum = 0.f;
#pragma unroll
        for (int r = 0; r < 8; r++) {
            float4 v0 = *reinterpret_cast<const float4*>(p + (size_t)r * 128);
            float4 v1 = *reinterpret_cast<const float4*>(p + (size_t)r * 128 + 4);
            sum += (v0.x + v0.y + v0.z + v0.w) + (v1.x + v1.y + v1.z + v1.w);
        }
        sc[c][s] = sum * (1.f / 64.f);
    }
    __syncthreads();

    // ---- Phase 2: normalized point-centers + init cluster accumulators
    if (tid < 64) {
        int s = tid;
        float ss = 0.f;
#pragma unroll
        for (int j = 0; j < 32; j++) { float v = sc[j][s]; ss += v * v; }
        float inv = 1.f / fmaxf(sqrtf(ss), 1e-12f);
#pragma unroll
        for (int j = 0; j < 32; j++) cpn[s][j] = sc[j][s] * inv;
    }
    for (int i = tid; i < 64 * 33; i += 256) {
        int s = i / 33, j = i % 33;
        ncs[s][j] = (j < 32) ? sc[32 + j][s] : 1.0f;
    }
    __syncthreads();

    // ---- Phase 3+4: sim/argmax/sigmoid, then scatter-add (own pixels)
#pragma unroll 1
    for (int i = 0; i < 16; i++) {
        int l = i * 256 + tid;
        int hh = l >> 6, ww = l & 63;
        const float* px = g_y + ybase + (size_t)(roff + hh) * 128 + (coff + ww);
        float xp[32];
#pragma unroll
        for (int j = 0; j < 32; j++) xp[j] = px[(size_t)j * HWS];
        float ss = 0.f;
#pragma unroll
        for (int j = 0; j < 32; j++) ss += xp[j] * xp[j];
        float inv = 1.f / fmaxf(sqrtf(ss), 1e-12f);

        float best = -3.4e38f; int bi = 0;
#pragma unroll 1
        for (int s = 0; s < 64; s++) {
            float d = 0.f;
#pragma unroll
            for (int j = 0; j < 32; j++) d = fmaf(xp[j], cpn[s][j], d);
            float q = al * d;
            if (q > best) { best = q; bi = s; }
        }
        float val = 1.f / (1.f + expf(-(best * inv + be)));
        svals[l] = __float2half_rn(val);
        sidx[l]  = (unsigned char)bi;

        // scatter: value channels 32..63
#pragma unroll
        for (int j = 0; j < 32; j++) {
            float xv = px[(size_t)(32 + j) * HWS];
            atomicAdd(&ncs[bi][j], val * xv);
        }
        atomicAdd(&ncs[bi][32], val);
    }
    __syncthreads();

    // ---- Phase 5: normalize clusters into cpn (reuse)
    for (int i = tid; i < 2048; i += 256) {
        int s = i >> 5, j = i & 31;
        cpn[s][j] = ncs[s][j] / ncs[s][32];
    }
    __syncthreads();

    // ---- Phase 6: gather + write to g_nx in final (n, FC*cv, H, W) layout
    const size_t obase = ((size_t)n * 256 + (size_t)f * 32) * HWS;
#pragma unroll 1
    for (int i = 0; i < 16; i++) {
        int l = i * 256 + tid;
        int hh = l >> 6, ww = l & 63;
        float v = __half2float(svals[l]);
        int s = sidx[l];
        size_t ob = obase + (size_t)(roff + hh) * 128 + (coff + ww);
#pragma unroll
        for (int j = 0; j < 32; j++)
            g_nx[ob + (size_t)j * HWS] = v * cpn[s][j];
    }
}

// ---------------------------------------------------------------------------
// GroupNorm(1 group) reductions: per-n mean/var over 256*HW elements
// ---------------------------------------------------------------------------
template<int SRCSEL, int WHICH>
__global__ void __launch_bounds__(256) gn_reduce()
{
    const float* src = SRCSEL ? g_t : g_newx;
    const int n = blockIdx.y, ch = blockIdx.x;
    const size_t base = (size_t)n * PERN + (size_t)ch * 65536;
    float s = 0.f, q = 0.f;
    for (int i = threadIdx.x; i < 16384; i += 256) {
        float4 v = *reinterpret_cast<const float4*>(src + base + (size_t)i * 4);
        s += (v.x + v.y) + (v.z + v.w);
        q += (v.x * v.x + v.y * v.y) + (v.z * v.z + v.w * v.w);
    }
    __shared__ float rs[256], rq[256];
    rs[threadIdx.x] = s; rq[threadIdx.x] = q;
    __syncthreads();
    for (int off = 128; off > 0; off >>= 1) {
        if (threadIdx.x < off) {
            rs[threadIdx.x] += rs[threadIdx.x + off];
            rq[threadIdx.x] += rq[threadIdx.x + off];
        }
        __syncthreads();
    }
    if (threadIdx.x == 0) {
        g_psum[WHICH][n][ch] = (double)rs[0];
        g_psq[WHICH][n][ch]  = (double)rq[0];
    }
}

template<int WHICH>
__global__ void gn_finish()
{
    int t = threadIdx.x;
    if (t < NB) {
        double s = 0.0, q = 0.0;
        for (int ch = 0; ch < 64; ch++) { s += g_psum[WHICH][t][ch]; q += g_psq[WHICH][t][ch]; }
        double cnt = (double)PERN;
        double mu = s / cnt;
        double var = q / cnt - mu * mu;
        g_stat[WHICH][t][0] = (float)mu;
        g_stat[WHICH][t][1] = (float)(1.0 / sqrt(var + 1e-5));
    }
}

// normalize g_newx in place with g0 affine
__global__ void __launch_bounds__(256)
gn_apply0(const float* __restrict__ w, const float* __restrict__ b)
{
    size_t gid = (size_t)blockIdx.x * 256 + threadIdx.x;
    size_t base = gid * 4;
    int n = (int)(base >> 22);
    int c = (int)(base >> 14) & 255;
    float mu = g_stat[0][n][0], rstd = g_stat[0][n][1];
    float sc = rstd * w[c];
    float bi = b[c] - mu * sc;
    float4 v = *reinterpret_cast<float4*>(&g_newx[base]);
    v.x = v.x * sc + bi; v.y = v.y * sc + bi; v.z = v.z * sc + bi; v.w = v.w * sc + bi;
    *reinterpret_cast<float4*>(&g_newx[base]) = v;
}

// final: out = gn1(t)*layer_scale + x
__global__ void __launch_bounds__(256)
final_kernel(const float* __restrict__ x, const float* __restrict__ w,
             const float* __restrict__ b, const float* __restrict__ ls,
             float* __restrict__ out)
{
    size_t gid = (size_t)blockIdx.x * 256 + threadIdx.x;
    size_t base = gid * 4;
    int n = (int)(base >> 22);
    int c = (int)(base >> 14) & 255;
    float mu = g_stat[1][n][0], rstd = g_stat[1][n][1];
    float lsc = ls[c];
    float sc = rstd * w[c] * lsc;
    float bi = (b[c] - mu * rstd * w[c]) * lsc;
    float4 t = *reinterpret_cast<const float4*>(&g_t[base]);
    float4 xv = *reinterpret_cast<const float4*>(&x[base]);
    float4 o;
    o.x = t.x * sc + bi + xv.x;
    o.y = t.y * sc + bi + xv.y;
    o.z = t.z * sc + bi + xv.z;
    o.w = t.w * sc + bi + xv.w;
    *reinterpret_cast<float4*>(&out[base]) = o;
}

// ---------------------------------------------------------------------------
// Launch
// ---------------------------------------------------------------------------
extern "C" void kernel_launch(void* const* d_in, const int* in_sizes, int n_in,
                              void* d_out, int out_size)
{
    const float* x        = (const float*)d_in[0];
    const float* proj_w   = (const float*)d_in[1];
    const float* proj_b   = (const float*)d_in[2];
    const float* merge_w  = (const float*)d_in[3];
    const float* merge_b  = (const float*)d_in[4];
    const float* alpha    = (const float*)d_in[5];
    const float* beta     = (const float*)d_in[6];
    const float* g0_w     = (const float*)d_in[7];
    const float* g0_b     = (const float*)d_in[8];
    const float* mlp_w0   = (const float*)d_in[9];
    const float* mlp_b0   = (const float*)d_in[10];
    const float* mlp_w1   = (const float*)d_in[11];
    const float* mlp_b1   = (const float*)d_in[12];
    const float* g1_w     = (const float*)d_in[13];
    const float* g1_b     = (const float*)d_in[14];
    const float* lscale   = (const float*)d_in[15];
    float* out = (float*)d_out;

    // 1) proj: y = proj_w @ x + proj_b   (512x256 @ 256x16384 per n)
    sgemm_kernel<256, 512, false, false, 0, 0><<<dim3(128, 4, NB), 256>>>(proj_w, x, proj_b);

    // 2) local clustering (fused)
    cluster_kernel<<<256, 256>>>(alpha, beta);

    // 3) merge: newx = merge_w @ nx + merge_b
    sgemm_kernel<256, 256, false, false, 1, 1><<<dim3(128, 2, NB), 256>>>(merge_w, nullptr, merge_b);

    // 4) group-norm 0 on newx (in place)
    gn_reduce<0, 0><<<dim3(64, NB), 256>>>();
    gn_finish<0><<<1, 32>>>();
    gn_apply0<<<32768, 256>>>(g0_w, g0_b);

    // 5) MLP: hidden = gelu(W0^T @ [x; newx] + b0) -> g_y ; t = W1^T @ hidden + b1 -> g_t
    sgemm_kernel<512, 512, true, true,  2, 0><<<dim3(128, 4, NB), 256>>>(mlp_w0, x, mlp_b0);
    sgemm_kernel<512, 256, true, false, 3, 2><<<dim3(128, 2, NB), 256>>>(mlp_w1, nullptr, mlp_b1);

    // 6) group-norm 1 + layer_scale + residual
    gn_reduce<1, 1><<<dim3(64, NB), 256>>>();
    gn_finish<1><<<1, 32>>>();
    final_kernel<<<32768, 256>>>(x, g1_w, g1_b, lscale, out);

    (void)in_sizes; (void)n_in; (void)out_size;
}

// round 3
// speedup vs baseline: 3.0885x; 3.0885x over previous
#include <cuda_runtime.h>
#include <cuda_bf16.h>
#include <cuda_fp16.h>
#include <math.h>
#include <stdint.h>

#define HWC 16384
#define HWS ((size_t)HWC)
#define NB 8
#define PERN ((size_t)256*HWS)

// ---------------------------------------------------------------------------
// Scratch (device globals; no allocation allowed)
// ---------------------------------------------------------------------------
__device__ __align__(256) __nv_bfloat16 g_xb[(size_t)NB * 256 * HWC];   // x in bf16 (64MB)
__device__ __align__(256) __nv_bfloat16 g_y [(size_t)NB * 512 * HWC];   // proj out / mlp hidden (128MB)
__device__ __align__(256) __nv_bfloat16 g_nx[(size_t)NB * 256 * HWC];   // cluster out (64MB)
__device__ __align__(256) __nv_bfloat16 g_newx[(size_t)NB * 256 * HWC]; // merge out (64MB)
__device__ __align__(256) __nv_bfloat16 g_t [(size_t)NB * 256 * HWC];   // mlp out (64MB)

__device__ __align__(256) __nv_bfloat16 wb_proj[512 * 256];
__device__ __align__(256) __nv_bfloat16 wb_merge[256 * 256];
__device__ __align__(256) __nv_bfloat16 wb_mlp0[512 * 512];  // [out][in] (transposed)
__device__ __align__(256) __nv_bfloat16 wb_mlp1[256 * 512];  // [out][in] (transposed)

__device__ float2 g_part[2][NB][256];   // per-block GN partials (sum, sumsq)
__device__ float  g_stat[2][NB][2];     // mu, rstd

// ---------------------------------------------------------------------------
// Converters
// ---------------------------------------------------------------------------
__global__ void __launch_bounds__(256)
convert_weights(const float* __restrict__ pw, const float* __restrict__ mw,
                const float* __restrict__ w0, const float* __restrict__ w1)
{
    int i = blockIdx.x * 256 + threadIdx.x;
    if (i < 512 * 256) wb_proj[i]  = __float2bfloat16(pw[i]);
    if (i < 256 * 256) wb_merge[i] = __float2bfloat16(mw[i]);
    if (i < 512 * 512) { int o = i >> 9, k = i & 511; wb_mlp0[i] = __float2bfloat16(w0[(size_t)k * 512 + o]); }
    if (i < 256 * 512) { int o = i >> 9, k = i & 511; wb_mlp1[i] = __float2bfloat16(w1[(size_t)k * 256 + o]); }
}

__global__ void __launch_bounds__(256)
convert_x(const float* __restrict__ x)
{
    size_t base = ((size_t)blockIdx.x * 256 + threadIdx.x) * 8;
    float4 v0 = *reinterpret_cast<const float4*>(x + base);
    float4 v1 = *reinterpret_cast<const float4*>(x + base + 4);
    union { uint4 u; __nv_bfloat162 h[4]; } pk;
    pk.h[0] = __floats2bfloat162_rn(v0.x, v0.y);
    pk.h[1] = __floats2bfloat162_rn(v0.z, v0.w);
    pk.h[2] = __floats2bfloat162_rn(v1.x, v1.y);
    pk.h[3] = __floats2bfloat162_rn(v1.z, v1.w);
    *reinterpret_cast<uint4*>(g_xb + base) = pk.u;
}

// ---------------------------------------------------------------------------
// bf16 tensor-core GEMM: C[n] (MM x 16384) = A (MM x KK) * B[n] + bias
// Tiles: BM=128, BN=128, BK=32. 256 threads = 8 warps (2 M x 4 N), each warp
// 64x32 via 4x4 mma.m16n8k16. Grid: (MM/128, 128, NB) — row-blocks fastest
// so B col-tiles get L2 reuse across row-blocks.
// BSRC: 0=g_xb  1=g_nx  2=concat(g_xb, gn0-affine(g_newx))  3=g_y(512 rows)
// CSEL: 0=g_y  1=g_newx  2=g_t.  GNW: -1 none, 0/1 write GN partials.
// ---------------------------------------------------------------------------
template<int KK, int MM, bool GELU, int BSRC, int CSEL, int GNW>
__global__ void __launch_bounds__(256)
mma_gemm(const float* __restrict__ bias,
         const float* __restrict__ gw, const float* __restrict__ gb)
{
    __shared__ __nv_bfloat16 As[128][40];   // padded: conflict-free ldmatrix
    __shared__ __nv_bfloat16 Bs[32][136];
    __shared__ float red[16];

    const __nv_bfloat16* A =
        (BSRC == 0) ? wb_proj : (BSRC == 1) ? wb_merge : (BSRC == 2) ? wb_mlp0 : wb_mlp1;

    const int tid  = threadIdx.x;
    const int lane = tid & 31, wid = tid >> 5;
    const int warpM = wid & 1, warpN = wid >> 1;
    const int row0 = blockIdx.x * 128;
    const int col0 = blockIdx.y * 128;
    const int n    = blockIdx.z;

    float mu0 = 0.f, rs0 = 1.f;
    if (BSRC == 2) { mu0 = g_stat[0][n][0]; rs0 = g_stat[0][n][1]; }

    uint4 ra[2], rb[2];

    auto load_tiles = [&](int kt) {
#pragma unroll
        for (int i = 0; i < 2; i++) {
            int idx = tid + i * 256;            // A: 128 rows x 4 chunks
            int r = idx >> 2, cp = (idx & 3) * 8;
            ra[i] = *reinterpret_cast<const uint4*>(A + (size_t)(row0 + r) * KK + kt * 32 + cp);
        }
#pragma unroll
        for (int i = 0; i < 2; i++) {
            int idx = tid + i * 256;            // B: 32 rows x 16 chunks
            int r = idx >> 4, cp = (idx & 15) * 8;
            int krow = kt * 32 + r;
            const __nv_bfloat16* bp;
            if (BSRC == 0)      bp = g_xb  + ((size_t)n * 256 + krow) * HWS;
            else if (BSRC == 1) bp = g_nx  + ((size_t)n * 256 + krow) * HWS;
            else if (BSRC == 2) bp = (krow < 256)
                                   ? (g_xb   + ((size_t)n * 256 + krow) * HWS)
                                   : (g_newx + ((size_t)n * 256 + (krow - 256)) * HWS);
            else                bp = g_y   + ((size_t)n * 512 + krow) * HWS;
            uint4 v = *reinterpret_cast<const uint4*>(bp + col0 + cp);
            if (BSRC == 2 && krow >= 256) {     // fused GN0 affine
                int c = krow - 256;
                float sc = rs0 * gw[c];
                float bi = gb[c] - mu0 * sc;
                union { uint4 u; __nv_bfloat162 h[4]; } pk; pk.u = v;
#pragma unroll
                for (int j = 0; j < 4; j++) {
                    float2 f = __bfloat1622float2(pk.h[j]);
                    pk.h[j] = __floats2bfloat162_rn(f.x * sc + bi, f.y * sc + bi);
                }
                v = pk.u;
            }
            rb[i] = v;
        }
    };

    float acc[4][4][4];
#pragma unroll
    for (int a = 0; a < 4; a++)
#pragma unroll
        for (int b = 0; b < 4; b++)
#pragma unroll
            for (int c = 0; c < 4; c++) acc[a][b][c] = 0.f;

    const int KT = KK / 32;
    load_tiles(0);
    for (int kt = 0; kt < KT; kt++) {
#pragma unroll
        for (int i = 0; i < 2; i++) {
            int idx = tid + i * 256;
            int r = idx >> 2, cp = (idx & 3) * 8;
            *reinterpret_cast<uint4*>(&As[r][cp]) = ra[i];
        }
#pragma unroll
        for (int i = 0; i < 2; i++) {
            int idx = tid + i * 256;
            int r = idx >> 4, cp = (idx & 15) * 8;
            *reinterpret_cast<uint4*>(&Bs[r][cp]) = rb[i];
        }
        __syncthreads();
        if (kt + 1 < KT) load_tiles(kt + 1);

#pragma unroll
        for (int ks = 0; ks < 2; ks++) {
            uint32_t af[4][4];
#pragma unroll
            for (int mi = 0; mi < 4; mi++) {
                int r = warpM * 64 + mi * 16 + (lane & 7) + ((lane >> 3) & 1) * 8;
                int c = ks * 16 + (lane >> 4) * 8;
                uint32_t addr = (uint32_t)__cvta_generic_to_shared(&As[r][c]);
                asm volatile("ldmatrix.sync.aligned.m8n8.x4.shared.b16 {%0,%1,%2,%3},[%4];"
                             : "=r"(af[mi][0]), "=r"(af[mi][1]), "=r"(af[mi][2]), "=r"(af[mi][3])
                             : "r"(addr));
            }
            uint32_t bfr[4][2];
#pragma unroll
            for (int nj = 0; nj < 2; nj++) {
                int k = ks * 16 + (lane & 7) + ((lane >> 3) & 1) * 8;
                int c = warpN * 32 + nj * 16 + (lane >> 4) * 8;
                uint32_t addr = (uint32_t)__cvta_generic_to_shared(&Bs[k][c]);
                uint32_t r0, r1, r2, r3;
                asm volatile("ldmatrix.sync.aligned.m8n8.x4.trans.shared.b16 {%0,%1,%2,%3},[%4];"
                             : "=r"(r0), "=r"(r1), "=r"(r2), "=r"(r3) : "r"(addr));
                bfr[nj * 2][0] = r0; bfr[nj * 2][1] = r1;
                bfr[nj * 2 + 1][0] = r2; bfr[nj * 2 + 1][1] = r3;
            }
#pragma unroll
            for (int mi = 0; mi < 4; mi++)
#pragma unroll
                for (int ni = 0; ni < 4; ni++) {
                    float* c = acc[mi][ni];
                    asm volatile(
                        "mma.sync.aligned.m16n8k16.row.col.f32.bf16.bf16.f32 "
                        "{%0,%1,%2,%3},{%4,%5,%6,%7},{%8,%9},{%0,%1,%2,%3};"
                        : "+f"(c[0]), "+f"(c[1]), "+f"(c[2]), "+f"(c[3])
                        : "r"(af[mi][0]), "r"(af[mi][1]), "r"(af[mi][2]), "r"(af[mi][3]),
                          "r"(bfr[ni][0]), "r"(bfr[ni][1]));
                }
        }
        __syncthreads();
    }

    // ---- epilogue: bias (+gelu), bf16 store, optional GN partials
    __nv_bfloat16* C = (CSEL == 0) ? g_y : (CSEL == 1) ? g_newx : g_t;
    const int g = lane >> 2, t4 = lane & 3;
    float gsum = 0.f, gsq = 0.f;
#pragma unroll
    for (int mi = 0; mi < 4; mi++) {
        int r = row0 + warpM * 64 + mi * 16 + g;
        float b0 = bias[r], b1 = bias[r + 8];
#pragma unroll
        for (int ni = 0; ni < 4; ni++) {
            int c = col0 + warpN * 32 + ni * 8 + t4 * 2;
            float u0 = acc[mi][ni][0] + b0;
            float u1 = acc[mi][ni][1] + b0;
            float u2 = acc[mi][ni][2] + b1;
            float u3 = acc[mi][ni][3] + b1;
            if (GELU) {
                u0 *= normcdff(u0); u1 *= normcdff(u1);
                u2 *= normcdff(u2); u3 *= normcdff(u3);
            }
            if (GNW >= 0) {
                gsum += (u0 + u1) + (u2 + u3);
                gsq  += (u0 * u0 + u1 * u1) + (u2 * u2 + u3 * u3);
            }
            size_t o0 = ((size_t)n * MM + r) * HWS + c;
            size_t o1 = ((size_t)n * MM + r + 8) * HWS + c;
            *reinterpret_cast<__nv_bfloat162*>(&C[o0]) = __floats2bfloat162_rn(u0, u1);
            *reinterpret_cast<__nv_bfloat162*>(&C[o1]) = __floats2bfloat162_rn(u2, u3);
        }
    }
    if (GNW >= 0) {
#pragma unroll
        for (int o = 16; o; o >>= 1) {
            gsum += __shfl_xor_sync(0xffffffffu, gsum, o);
            gsq  += __shfl_xor_sync(0xffffffffu, gsq,  o);
        }
        if (lane == 0) { red[wid] = gsum; red[8 + wid] = gsq; }
        __syncthreads();
        if (tid == 0) {
            float s = 0.f, q = 0.f;
#pragma unroll
            for (int w = 0; w < 8; w++) { s += red[w]; q += red[8 + w]; }
            g_part[GNW][n][blockIdx.x * 128 + blockIdx.y] = make_float2(s, q);
        }
    }
}

// ---------------------------------------------------------------------------
// gn_finish: reduce 256 per-block partials per n -> (mu, rstd)
// ---------------------------------------------------------------------------
template<int W>
__global__ void gn_finish()
{
    int lane = threadIdx.x & 31, w = threadIdx.x >> 5;  // w = n
    double s = 0.0, q = 0.0;
    for (int i = lane; i < 256; i += 32) {
        float2 p = g_part[W][w][i];
        s += (double)p.x; q += (double)p.y;
    }
#pragma unroll
    for (int o = 16; o; o >>= 1) {
        s += __shfl_xor_sync(0xffffffffu, s, o);
        q += __shfl_xor_sync(0xffffffffu, q, o);
    }
    if (lane == 0) {
        double cnt = (double)PERN;
        double mu = s / cnt;
        double var = q / cnt - mu * mu;
        g_stat[W][w][0] = (float)mu;
        g_stat[W][w][1] = (float)(1.0 / sqrt(var + 1e-5));
    }
}

// ---------------------------------------------------------------------------
// Fused local-cluster kernel (reads bf16 g_y, writes bf16 g_nx)
// ---------------------------------------------------------------------------
__global__ void __launch_bounds__(256)
cluster_kernel(const float* __restrict__ alpha_p, const float* __restrict__ beta_p)
{
    __shared__ float sc[64][64];
    __shared__ float cpn[64][33];
    __shared__ __half svals[4096];
    __shared__ unsigned char sidx[4096];
    __shared__ float ncs[64][33];

    const int tid = threadIdx.x;
    const int m = blockIdx.x;
    const int n   = m >> 5;
    const int f   = (m >> 2) & 7;
    const int fs1 = (m >> 1) & 1;
    const int fs2 = m & 1;
    const int roff = fs1 * 64, coff = fs2 * 64;
    const size_t ybase = ((size_t)n * 512 + (size_t)f * 64) * HWS;

    const float al = alpha_p[0];
    const float be = beta_p[0];

    // Phase 1: 8x8 pooled centers
#pragma unroll 1
    for (int i = 0; i < 16; i++) {
        int pi = i * 256 + tid;
        int c = pi >> 6, s = pi & 63;
        int a = s >> 3, b = s & 7;
        const __nv_bfloat16* p = g_y + ybase + (size_t)c * HWS + (size_t)(roff + a * 8) * 128 + coff + b * 8;
        float sum = 0.f;
#pragma unroll
        for (int r = 0; r < 8; r++) {
            union { uint4 u; __nv_bfloat162 h[4]; } pk;
            pk.u = *reinterpret_cast<const uint4*>(p + (size_t)r * 128);
#pragma unroll
            for (int j = 0; j < 4; j++) {
                float2 f2 = __bfloat1622float2(pk.h[j]);
                sum += f2.x + f2.y;
            }
        }
        sc[c][s] = sum * (1.f / 64.f);
    }
    __syncthreads();

    // Phase 2: normalized point-centers + cluster accumulator init
    if (tid < 64) {
        int s = tid;
        float ss = 0.f;
#pragma unroll
        for (int j = 0; j < 32; j++) { float v = sc[j][s]; ss += v * v; }
        float inv = 1.f / fmaxf(sqrtf(ss), 1e-12f);
#pragma unroll
        for (int j = 0; j < 32; j++) cpn[s][j] = sc[j][s] * inv;
    }
    for (int i = tid; i < 64 * 33; i += 256) {
        int s = i / 33, j = i % 33;
        ncs[s][j] = (j < 32) ? sc[32 + j][s] : 1.0f;
    }
    __syncthreads();

    // Phase 3+4: sim/argmax/sigmoid + scatter
#pragma unroll 1
    for (int i = 0; i < 16; i++) {
        int l = i * 256 + tid;
        int hh = l >> 6, ww = l & 63;
        const __nv_bfloat16* px = g_y + ybase + (size_t)(roff + hh) * 128 + (coff + ww);
        float xp[32];
#pragma unroll
        for (int j = 0; j < 32; j++) xp[j] = __bfloat162float(px[(size_t)j * HWS]);
        float ss = 0.f;
#pragma unroll
        for (int j = 0; j < 32; j++) ss += xp[j] * xp[j];
        float inv = 1.f / fmaxf(sqrtf(ss), 1e-12f);

        float best = -3.4e38f; int bi = 0;
#pragma unroll 1
        for (int s = 0; s < 64; s++) {
            float d = 0.f;
#pragma unroll
            for (int j = 0; j < 32; j++) d = fmaf(xp[j], cpn[s][j], d);
            if (d > best) { best = d; bi = s; }
        }
        float val = 1.f / (1.f + expf(-(al * best * inv + be)));
        svals[l] = __float2half_rn(val);
        sidx[l]  = (unsigned char)bi;

#pragma unroll
        for (int j = 0; j < 32; j++) {
            float xv = __bfloat162float(px[(size_t)(32 + j) * HWS]);
            atomicAdd(&ncs[bi][j], val * xv);
        }
        atomicAdd(&ncs[bi][32], val);
    }
    __syncthreads();

    // Phase 5: normalize clusters
    for (int i = tid; i < 2048; i += 256) {
        int s = i >> 5, j = i & 31;
        cpn[s][j] = ncs[s][j] / ncs[s][32];
    }
    __syncthreads();

    // Phase 6: gather + write
    const size_t obase = ((size_t)n * 256 + (size_t)f * 32) * HWS;
#pragma unroll 1
    for (int i = 0; i < 16; i++) {
        int l = i * 256 + tid;
        int hh = l >> 6, ww = l & 63;
        float v = __half2float(svals[l]);
        int s = sidx[l];
        size_t ob = obase + (size_t)(roff + hh) * 128 + (coff + ww);
#pragma unroll
        for (int j = 0; j < 32; j++)
            g_nx[ob + (size_t)j * HWS] = __float2bfloat16(v * cpn[s][j]);
    }
}

// ---------------------------------------------------------------------------
// final: out = gn1(t)*layer_scale + x
// ---------------------------------------------------------------------------
__global__ void __launch_bounds__(256)
final_kernel(const float* __restrict__ x, const float* __restrict__ w,
             const float* __restrict__ b, const float* __restrict__ ls,
             float* __restrict__ out)
{
    size_t base = ((size_t)blockIdx.x * 256 + threadIdx.x) * 8;
    int n = (int)(base >> 22);
    int c = (int)(base >> 14) & 255;
    float mu = g_stat[1][n][0], rstd = g_stat[1][n][1];
    float lsc = ls[c];
    float scale = rstd * w[c] * lsc;
    float bi = (b[c] - mu * rstd * w[c]) * lsc;

    union { uint4 u; __nv_bfloat162 h[4]; } pk;
    pk.u = *reinterpret_cast<const uint4*>(g_t + base);
    float4 x0 = *reinterpret_cast<const float4*>(x + base);
    float4 x1 = *reinterpret_cast<const float4*>(x + base + 4);
    float t[8];
#pragma unroll
    for (int j = 0; j < 4; j++) {
        float2 f2 = __bfloat1622float2(pk.h[j]);
        t[j * 2] = f2.x; t[j * 2 + 1] = f2.y;
    }
    float4 o0, o1;
    o0.x = t[0] * scale + bi + x0.x;
    o0.y = t[1] * scale + bi + x0.y;
    o0.z = t[2] * scale + bi + x0.z;
    o0.w = t[3] * scale + bi + x0.w;
    o1.x = t[4] * scale + bi + x1.x;
    o1.y = t[5] * scale + bi + x1.y;
    o1.z = t[6] * scale + bi + x1.z;
    o1.w = t[7] * scale + bi + x1.w;
    *reinterpret_cast<float4*>(out + base)     = o0;
    *reinterpret_cast<float4*>(out + base + 4) = o1;
}

// ---------------------------------------------------------------------------
// Launch
// ---------------------------------------------------------------------------
extern "C" void kernel_launch(void* const* d_in, const int* in_sizes, int n_in,
                              void* d_out, int out_size)
{
    const float* x        = (const float*)d_in[0];
    const float* proj_w   = (const float*)d_in[1];
    const float* proj_b   = (const float*)d_in[2];
    const float* merge_w  = (const float*)d_in[3];
    const float* merge_b  = (const float*)d_in[4];
    const float* alpha    = (const float*)d_in[5];
    const float* beta     = (const float*)d_in[6];
    const float* g0_w     = (const float*)d_in[7];
    const float* g0_b     = (const float*)d_in[8];
    const float* mlp_w0   = (const float*)d_in[9];
    const float* mlp_b0   = (const float*)d_in[10];
    const float* mlp_w1   = (const float*)d_in[11];
    const float* mlp_b1   = (const float*)d_in[12];
    const float* g1_w     = (const float*)d_in[13];
    const float* g1_b     = (const float*)d_in[14];
    const float* lscale   = (const float*)d_in[15];
    float* out = (float*)d_out;

    convert_weights<<<1024, 256>>>(proj_w, merge_w, mlp_w0, mlp_w1);
    convert_x<<<16384, 256>>>(x);

    // proj: y = proj_w @ x + proj_b
    mma_gemm<256, 512, false, 0, 0, -1><<<dim3(4, 128, NB), 256>>>(proj_b, nullptr, nullptr);

    // local clustering
    cluster_kernel<<<256, 256>>>(alpha, beta);

    // merge (+GN0 partials)
    mma_gemm<256, 256, false, 1, 1, 0><<<dim3(2, 128, NB), 256>>>(merge_b, nullptr, nullptr);
    gn_finish<0><<<1, 256>>>();

    // MLP (GN0 affine fused into B-load of mlp0)
    mma_gemm<512, 512, true,  2, 0, -1><<<dim3(4, 128, NB), 256>>>(mlp_b0, g0_w, g0_b);
    mma_gemm<512, 256, false, 3, 2,  1><<<dim3(2, 128, NB), 256>>>(mlp_b1, nullptr, nullptr);
    gn_finish<1><<<1, 256>>>();

    final_kernel<<<16384, 256>>>(x, g1_w, g1_b, lscale, out);

    (void)in_sizes; (void)n_in; (void)out_size;
}

// round 7
// speedup vs baseline: 4.0132x; 1.2994x over previous
#include <cuda_runtime.h>
#include <cuda_bf16.h>
#include <cuda_fp16.h>
#include <math.h>
#include <stdint.h>

#define HWC 16384
#define HWS ((size_t)HWC)
#define NB 8
#define PERN ((size_t)256*HWS)

// ---------------------------------------------------------------------------
// Scratch (device globals; no allocation allowed)
// ---------------------------------------------------------------------------
__device__ __align__(256) __nv_bfloat16 g_xb[(size_t)NB * 256 * HWC];
__device__ __align__(256) __nv_bfloat16 g_y [(size_t)NB * 512 * HWC];
__device__ __align__(256) __nv_bfloat16 g_nx[(size_t)NB * 256 * HWC];
__device__ __align__(256) __nv_bfloat16 g_newx[(size_t)NB * 256 * HWC];
__device__ __align__(256) __nv_bfloat16 g_t [(size_t)NB * 256 * HWC];

__device__ __align__(256) __nv_bfloat16 wb_proj[512 * 256];
__device__ __align__(256) __nv_bfloat16 wb_merge[256 * 256];
__device__ __align__(256) __nv_bfloat16 wb_mlp0[512 * 512];
__device__ __align__(256) __nv_bfloat16 wb_mlp1[256 * 512];

__device__ float2 g_part[2][NB][256];
__device__ float  g_stat[2][NB][2];

// ---------------------------------------------------------------------------
// Converters
// ---------------------------------------------------------------------------
__global__ void __launch_bounds__(256)
convert_weights(const float* __restrict__ pw, const float* __restrict__ mw,
                const float* __restrict__ w0, const float* __restrict__ w1)
{
    int i = blockIdx.x * 256 + threadIdx.x;
    if (i < 512 * 256) wb_proj[i]  = __float2bfloat16(pw[i]);
    if (i < 256 * 256) wb_merge[i] = __float2bfloat16(mw[i]);
    if (i < 512 * 512) { int o = i >> 9, k = i & 511; wb_mlp0[i] = __float2bfloat16(w0[(size_t)k * 512 + o]); }
    if (i < 256 * 512) { int o = i >> 9, k = i & 511; wb_mlp1[i] = __float2bfloat16(w1[(size_t)k * 256 + o]); }
}

__global__ void __launch_bounds__(256)
convert_x(const float* __restrict__ x)
{
    size_t base = ((size_t)blockIdx.x * 256 + threadIdx.x) * 8;
    float4 v0 = *reinterpret_cast<const float4*>(x + base);
    float4 v1 = *reinterpret_cast<const float4*>(x + base + 4);
    union { uint4 u; __nv_bfloat162 h[4]; } pk;
    pk.h[0] = __floats2bfloat162_rn(v0.x, v0.y);
    pk.h[1] = __floats2bfloat162_rn(v0.z, v0.w);
    pk.h[2] = __floats2bfloat162_rn(v1.x, v1.y);
    pk.h[3] = __floats2bfloat162_rn(v1.z, v1.w);
    *reinterpret_cast<uint4*>(g_xb + base) = pk.u;
}

// ---------------------------------------------------------------------------
// bf16 tensor-core GEMM, double-buffered smem.
// C[n] (MM x 16384) = A (MM x KK) * B[n] + bias
// BM=BN=128, BK=32, 256 threads = 8 warps (2Mx4N), warp does 64x32 via mma.
// ---------------------------------------------------------------------------
template<int KK, int MM, bool GELU, int BSRC, int CSEL, int GNW>
__global__ void __launch_bounds__(256)
mma_gemm(const float* __restrict__ bias,
         const float* __restrict__ gw, const float* __restrict__ gb)
{
    __shared__ __nv_bfloat16 As[2][128][40];
    __shared__ __nv_bfloat16 Bs[2][32][136];
    __shared__ float red[16];

    const __nv_bfloat16* A =
        (BSRC == 0) ? wb_proj : (BSRC == 1) ? wb_merge : (BSRC == 2) ? wb_mlp0 : wb_mlp1;

    const int tid  = threadIdx.x;
    const int lane = tid & 31, wid = tid >> 5;
    const int warpM = wid & 1, warpN = wid >> 1;
    const int row0 = blockIdx.x * 128;
    const int col0 = blockIdx.y * 128;
    const int n    = blockIdx.z;

    float mu0 = 0.f, rs0 = 1.f;
    if (BSRC == 2) { mu0 = g_stat[0][n][0]; rs0 = g_stat[0][n][1]; }

    uint4 ra[2], rb[2];

    auto load_tiles = [&](int kt) {
#pragma unroll
        for (int i = 0; i < 2; i++) {
            int idx = tid + i * 256;
            int r = idx >> 2, cp = (idx & 3) * 8;
            ra[i] = *reinterpret_cast<const uint4*>(A + (size_t)(row0 + r) * KK + kt * 32 + cp);
        }
#pragma unroll
        for (int i = 0; i < 2; i++) {
            int idx = tid + i * 256;
            int r = idx >> 4, cp = (idx & 15) * 8;
            int krow = kt * 32 + r;
            const __nv_bfloat16* bp;
            if (BSRC == 0)      bp = g_xb  + ((size_t)n * 256 + krow) * HWS;
            else if (BSRC == 1) bp = g_nx  + ((size_t)n * 256 + krow) * HWS;
            else if (BSRC == 2) bp = (krow < 256)
                                   ? (g_xb   + ((size_t)n * 256 + krow) * HWS)
                                   : (g_newx + ((size_t)n * 256 + (krow - 256)) * HWS);
            else                bp = g_y   + ((size_t)n * 512 + krow) * HWS;
            uint4 v = *reinterpret_cast<const uint4*>(bp + col0 + cp);
            if (BSRC == 2 && krow >= 256) {
                int c = krow - 256;
                float sc = rs0 * gw[c];
                float bi = gb[c] - mu0 * sc;
                union { uint4 u; __nv_bfloat162 h[4]; } pk; pk.u = v;
#pragma unroll
                for (int j = 0; j < 4; j++) {
                    float2 f = __bfloat1622float2(pk.h[j]);
                    pk.h[j] = __floats2bfloat162_rn(f.x * sc + bi, f.y * sc + bi);
                }
                v = pk.u;
            }
            rb[i] = v;
        }
    };

    auto store_tiles = [&](int buf) {
#pragma unroll
        for (int i = 0; i < 2; i++) {
            int idx = tid + i * 256;
            int r = idx >> 2, cp = (idx & 3) * 8;
            *reinterpret_cast<uint4*>(&As[buf][r][cp]) = ra[i];
        }
#pragma unroll
        for (int i = 0; i < 2; i++) {
            int idx = tid + i * 256;
            int r = idx >> 4, cp = (idx & 15) * 8;
            *reinterpret_cast<uint4*>(&Bs[buf][r][cp]) = rb[i];
        }
    };

    float acc[4][4][4];
#pragma unroll
    for (int a = 0; a < 4; a++)
#pragma unroll
        for (int b = 0; b < 4; b++)
#pragma unroll
            for (int c = 0; c < 4; c++) acc[a][b][c] = 0.f;

    const int KT = KK / 32;
    load_tiles(0);
    store_tiles(0);
    __syncthreads();

    for (int kt = 0; kt < KT; kt++) {
        const int cur = kt & 1;
        if (kt + 1 < KT) load_tiles(kt + 1);

#pragma unroll
        for (int ks = 0; ks < 2; ks++) {
            uint32_t af[4][4];
#pragma unroll
            for (int mi = 0; mi < 4; mi++) {
                int r = warpM * 64 + mi * 16 + (lane & 7) + ((lane >> 3) & 1) * 8;
                int c = ks * 16 + (lane >> 4) * 8;
                uint32_t addr = (uint32_t)__cvta_generic_to_shared(&As[cur][r][c]);
                asm volatile("ldmatrix.sync.aligned.m8n8.x4.shared.b16 {%0,%1,%2,%3},[%4];"
                             : "=r"(af[mi][0]), "=r"(af[mi][1]), "=r"(af[mi][2]), "=r"(af[mi][3])
                             : "r"(addr));
            }
            uint32_t bfr[4][2];
#pragma unroll
            for (int nj = 0; nj < 2; nj++) {
                int k = ks * 16 + (lane & 7) + ((lane >> 3) & 1) * 8;
                int c = warpN * 32 + nj * 16 + (lane >> 4) * 8;
                uint32_t addr = (uint32_t)__cvta_generic_to_shared(&Bs[cur][k][c]);
                uint32_t r0, r1, r2, r3;
                asm volatile("ldmatrix.sync.aligned.m8n8.x4.trans.shared.b16 {%0,%1,%2,%3},[%4];"
                             : "=r"(r0), "=r"(r1), "=r"(r2), "=r"(r3) : "r"(addr));
                bfr[nj * 2][0] = r0; bfr[nj * 2][1] = r1;
                bfr[nj * 2 + 1][0] = r2; bfr[nj * 2 + 1][1] = r3;
            }
#pragma unroll
            for (int mi = 0; mi < 4; mi++)
#pragma unroll
                for (int ni = 0; ni < 4; ni++) {
                    float* c = acc[mi][ni];
                    asm volatile(
                        "mma.sync.aligned.m16n8k16.row.col.f32.bf16.bf16.f32 "
                        "{%0,%1,%2,%3},{%4,%5,%6,%7},{%8,%9},{%0,%1,%2,%3};"
                        : "+f"(c[0]), "+f"(c[1]), "+f"(c[2]), "+f"(c[3])
                        : "r"(af[mi][0]), "r"(af[mi][1]), "r"(af[mi][2]), "r"(af[mi][3]),
                          "r"(bfr[ni][0]), "r"(bfr[ni][1]));
                }
        }
        if (kt + 1 < KT) store_tiles((kt + 1) & 1);
        __syncthreads();
    }

    __nv_bfloat16* C = (CSEL == 0) ? g_y : (CSEL == 1) ? g_newx : g_t;
    const int g = lane >> 2, t4 = lane & 3;
    float gsum = 0.f, gsq = 0.f;
#pragma unroll
    for (int mi = 0; mi < 4; mi++) {
        int r = row0 + warpM * 64 + mi * 16 + g;
        float b0 = bias[r], b1 = bias[r + 8];
#pragma unroll
        for (int ni = 0; ni < 4; ni++) {
            int c = col0 + warpN * 32 + ni * 8 + t4 * 2;
            float u0 = acc[mi][ni][0] + b0;
            float u1 = acc[mi][ni][1] + b0;
            float u2 = acc[mi][ni][2] + b1;
            float u3 = acc[mi][ni][3] + b1;
            if (GELU) {
                u0 *= normcdff(u0); u1 *= normcdff(u1);
                u2 *= normcdff(u2); u3 *= normcdff(u3);
            }
            if (GNW >= 0) {
                gsum += (u0 + u1) + (u2 + u3);
                gsq  += (u0 * u0 + u1 * u1) + (u2 * u2 + u3 * u3);
            }
            size_t o0 = ((size_t)n * MM + r) * HWS + c;
            size_t o1 = ((size_t)n * MM + r + 8) * HWS + c;
            *reinterpret_cast<__nv_bfloat162*>(&C[o0]) = __floats2bfloat162_rn(u0, u1);
            *reinterpret_cast<__nv_bfloat162*>(&C[o1]) = __floats2bfloat162_rn(u2, u3);
        }
    }
    if (GNW >= 0) {
#pragma unroll
        for (int o = 16; o; o >>= 1) {
            gsum += __shfl_xor_sync(0xffffffffu, gsum, o);
            gsq  += __shfl_xor_sync(0xffffffffu, gsq,  o);
        }
        if (lane == 0) { red[wid] = gsum; red[8 + wid] = gsq; }
        __syncthreads();
        if (tid == 0) {
            float s = 0.f, q = 0.f;
#pragma unroll
            for (int w = 0; w < 8; w++) { s += red[w]; q += red[8 + w]; }
            g_part[GNW][n][blockIdx.x * 128 + blockIdx.y] = make_float2(s, q);
        }
    }
}

// ---------------------------------------------------------------------------
template<int W>
__global__ void gn_finish()
{
    int lane = threadIdx.x & 31, w = threadIdx.x >> 5;
    double s = 0.0, q = 0.0;
    for (int i = lane; i < 256; i += 32) {
        float2 p = g_part[W][w][i];
        s += (double)p.x; q += (double)p.y;
    }
#pragma unroll
    for (int o = 16; o; o >>= 1) {
        s += __shfl_xor_sync(0xffffffffu, s, o);
        q += __shfl_xor_sync(0xffffffffu, q, o);
    }
    if (lane == 0) {
        double cnt = (double)PERN;
        double mu = s / cnt;
        double var = q / cnt - mu * mu;
        g_stat[W][w][0] = (float)mu;
        g_stat[W][w][1] = (float)(1.0 / sqrt(var + 1e-5));
    }
}

// ---------------------------------------------------------------------------
// Fused local-cluster kernel v2: float4 broadcast centers, 2 pixels/thread
// in the argmax loop, paired bf16x2 gather stores.
// ---------------------------------------------------------------------------
__global__ void __launch_bounds__(256, 2)
cluster_kernel(const float* __restrict__ alpha_p, const float* __restrict__ beta_p)
{
    __shared__ float sc[64][64];          // centers [c][s]
    __shared__ float4 cpn4[64][8];        // normalized point centers [s][j/4]
    __shared__ float cg[64][33];          // normalized cluster values
    __shared__ __half svals[4096];
    __shared__ unsigned char sidx[4096];
    __shared__ float ncs[64][33];

    const int tid = threadIdx.x;
    const int m = blockIdx.x;
    const int n   = m >> 5;
    const int f   = (m >> 2) & 7;
    const int fs1 = (m >> 1) & 1;
    const int fs2 = m & 1;
    const int roff = fs1 * 64, coff = fs2 * 64;
    const size_t ybase = ((size_t)n * 512 + (size_t)f * 64) * HWS;

    const float al = alpha_p[0];
    const float be = beta_p[0];

    // ---- Phase 1: 8x8 pooled centers (4096 (c,s) pairs, 16/thread)
#pragma unroll 1
    for (int i = 0; i < 16; i++) {
        int pi = i * 256 + tid;
        int c = pi >> 6, s = pi & 63;
        int a = s >> 3, b = s & 7;
        const __nv_bfloat16* p = g_y + ybase + (size_t)c * HWS + (size_t)(roff + a * 8) * 128 + coff + b * 8;
        float sum = 0.f;
#pragma unroll
        for (int r = 0; r < 8; r++) {
            union { uint4 u; __nv_bfloat162 h[4]; } pk;
            pk.u = *reinterpret_cast<const uint4*>(p + (size_t)r * 128);
#pragma unroll
            for (int j = 0; j < 4; j++) {
                float2 f2 = __bfloat1622float2(pk.h[j]);
                sum += f2.x + f2.y;
            }
        }
        sc[c][s] = sum * (1.f / 64.f);
    }
    __syncthreads();

    // ---- Phase 2: normalized point-centers (float4) + accumulator init
    if (tid < 64) {
        int s = tid;
        float ss = 0.f;
#pragma unroll
        for (int j = 0; j < 32; j++) { float v = sc[j][s]; ss += v * v; }
        float inv = 1.f / fmaxf(sqrtf(ss), 1e-12f);
#pragma unroll
        for (int j4 = 0; j4 < 8; j4++) {
            cpn4[s][j4] = make_float4(sc[j4 * 4 + 0][s] * inv, sc[j4 * 4 + 1][s] * inv,
                                      sc[j4 * 4 + 2][s] * inv, sc[j4 * 4 + 3][s] * inv);
        }
    }
    for (int i = tid; i < 64 * 33; i += 256) {
        int s = i / 33, j = i % 33;
        ncs[s][j] = (j < 32) ? sc[32 + j][s] : 1.0f;
    }
    __syncthreads();

    // ---- Phase 3+4: sim/argmax/sigmoid + scatter; 2 pixels per pass
#pragma unroll 1
    for (int i = 0; i < 8; i++) {
        int l0 = i * 512 + tid;
        int l1 = l0 + 256;
        const __nv_bfloat16* p0 = g_y + ybase + (size_t)(roff + (l0 >> 6)) * 128 + (coff + (l0 & 63));
        const __nv_bfloat16* p1 = g_y + ybase + (size_t)(roff + (l1 >> 6)) * 128 + (coff + (l1 & 63));

        float xp0[32], xp1[32];
#pragma unroll
        for (int j = 0; j < 32; j++) {
            xp0[j] = __bfloat162float(p0[(size_t)j * HWS]);
            xp1[j] = __bfloat162float(p1[(size_t)j * HWS]);
        }
        float ss0 = 0.f, ss1 = 0.f;
#pragma unroll
        for (int j = 0; j < 32; j++) { ss0 += xp0[j] * xp0[j]; ss1 += xp1[j] * xp1[j]; }
        float inv0 = 1.f / fmaxf(sqrtf(ss0), 1e-12f);
        float inv1 = 1.f / fmaxf(sqrtf(ss1), 1e-12f);

        float best0 = -3.4e38f, best1 = -3.4e38f;
        int b0 = 0, b1 = 0;
#pragma unroll 2
        for (int s = 0; s < 64; s++) {
            float d0 = 0.f, d1 = 0.f;
#pragma unroll
            for (int j4 = 0; j4 < 8; j4++) {
                float4 c = cpn4[s][j4];
                d0 = fmaf(xp0[j4 * 4 + 0], c.x, d0);
                d0 = fmaf(xp0[j4 * 4 + 1], c.y, d0);
                d0 = fmaf(xp0[j4 * 4 + 2], c.z, d0);
                d0 = fmaf(xp0[j4 * 4 + 3], c.w, d0);
                d1 = fmaf(xp1[j4 * 4 + 0], c.x, d1);
                d1 = fmaf(xp1[j4 * 4 + 1], c.y, d1);
                d1 = fmaf(xp1[j4 * 4 + 2], c.z, d1);
                d1 = fmaf(xp1[j4 * 4 + 3], c.w, d1);
            }
            if (d0 > best0) { best0 = d0; b0 = s; }
            if (d1 > best1) { best1 = d1; b1 = s; }
        }
        float val0 = 1.f / (1.f + expf(-(al * best0 * inv0 + be)));
        float val1 = 1.f / (1.f + expf(-(al * best1 * inv1 + be)));
        svals[l0] = __float2half_rn(val0); sidx[l0] = (unsigned char)b0;
        svals[l1] = __float2half_rn(val1); sidx[l1] = (unsigned char)b1;

#pragma unroll
        for (int j = 0; j < 32; j++) {
            float xv0 = __bfloat162float(p0[(size_t)(32 + j) * HWS]);
            float xv1 = __bfloat162float(p1[(size_t)(32 + j) * HWS]);
            atomicAdd(&ncs[b0][j], val0 * xv0);
            atomicAdd(&ncs[b1][j], val1 * xv1);
        }
        atomicAdd(&ncs[b0][32], val0);
        atomicAdd(&ncs[b1][32], val1);
    }
    __syncthreads();

    // ---- Phase 5: normalize clusters
    for (int i = tid; i < 2048; i += 256) {
        int s = i >> 5, j = i & 31;
        cg[s][j] = ncs[s][j] / ncs[s][32];
    }
    __syncthreads();

    // ---- Phase 6: gather + paired bf16x2 store
    const size_t obase = ((size_t)n * 256 + (size_t)f * 32) * HWS;
#pragma unroll 1
    for (int i = 0; i < 8; i++) {
        int l = (i * 256 + tid) * 2;          // even pixel; pair (l, l+1) same row
        int hh = l >> 6, ww = l & 63;
        float v0 = __half2float(svals[l]);
        float v1 = __half2float(svals[l + 1]);
        int s0 = sidx[l], s1 = sidx[l + 1];
        size_t ob = obase + (size_t)(roff + hh) * 128 + (coff + ww);
#pragma unroll
        for (int j = 0; j < 32; j++) {
            __nv_bfloat162 pk = __floats2bfloat162_rn(v0 * cg[s0][j], v1 * cg[s1][j]);
            *reinterpret_cast<__nv_bfloat162*>(&g_nx[ob + (size_t)j * HWS]) = pk;
        }
    }
}

// ---------------------------------------------------------------------------
__global__ void __launch_bounds__(256)
final_kernel(const float* __restrict__ x, const float* __restrict__ w,
             const float* __restrict__ b, const float* __restrict__ ls,
             float* __restrict__ out)
{
    size_t base = ((size_t)blockIdx.x * 256 + threadIdx.x) * 8;
    int n = (int)(base >> 22);
    int c = (int)(base >> 14) & 255;
    float mu = g_stat[1][n][0], rstd = g_stat[1][n][1];
    float lsc = ls[c];
    float scale = rstd * w[c] * lsc;
    float bi = (b[c] - mu * rstd * w[c]) * lsc;

    union { uint4 u; __nv_bfloat162 h[4]; } pk;
    pk.u = *reinterpret_cast<const uint4*>(g_t + base);
    float4 x0 = *reinterpret_cast<const float4*>(x + base);
    float4 x1 = *reinterpret_cast<const float4*>(x + base + 4);
    float t[8];
#pragma unroll
    for (int j = 0; j < 4; j++) {
        float2 f2 = __bfloat1622float2(pk.h[j]);
        t[j * 2] = f2.x; t[j * 2 + 1] = f2.y;
    }
    float4 o0, o1;
    o0.x = t[0] * scale + bi + x0.x;
    o0.y = t[1] * scale + bi + x0.y;
    o0.z = t[2] * scale + bi + x0.z;
    o0.w = t[3] * scale + bi + x0.w;
    o1.x = t[4] * scale + bi + x1.x;
    o1.y = t[5] * scale + bi + x1.y;
    o1.z = t[6] * scale + bi + x1.z;
    o1.w = t[7] * scale + bi + x1.w;
    *reinterpret_cast<float4*>(out + base)     = o0;
    *reinterpret_cast<float4*>(out + base + 4) = o1;
}

// ---------------------------------------------------------------------------
extern "C" void kernel_launch(void* const* d_in, const int* in_sizes, int n_in,
                              void* d_out, int out_size)
{
    const float* x        = (const float*)d_in[0];
    const float* proj_w   = (const float*)d_in[1];
    const float* proj_b   = (const float*)d_in[2];
    const float* merge_w  = (const float*)d_in[3];
    const float* merge_b  = (const float*)d_in[4];
    const float* alpha    = (const float*)d_in[5];
    const float* beta     = (const float*)d_in[6];
    const float* g0_w     = (const float*)d_in[7];
    const float* g0_b     = (const float*)d_in[8];
    const float* mlp_w0   = (const float*)d_in[9];
    const float* mlp_b0   = (const float*)d_in[10];
    const float* mlp_w1   = (const float*)d_in[11];
    const float* mlp_b1   = (const float*)d_in[12];
    const float* g1_w     = (const float*)d_in[13];
    const float* g1_b     = (const float*)d_in[14];
    const float* lscale   = (const float*)d_in[15];
    float* out = (float*)d_out;

    convert_weights<<<1024, 256>>>(proj_w, merge_w, mlp_w0, mlp_w1);
    convert_x<<<16384, 256>>>(x);

    mma_gemm<256, 512, false, 0, 0, -1><<<dim3(4, 128, NB), 256>>>(proj_b, nullptr, nullptr);

    cluster_kernel<<<256, 256>>>(alpha, beta);

    mma_gemm<256, 256, false, 1, 1, 0><<<dim3(2, 128, NB), 256>>>(merge_b, nullptr, nullptr);
    gn_finish<0><<<1, 256>>>();

    mma_gemm<512, 512, true,  2, 0, -1><<<dim3(4, 128, NB), 256>>>(mlp_b0, g0_w, g0_b);
    mma_gemm<512, 256, false, 3, 2,  1><<<dim3(2, 128, NB), 256>>>(mlp_b1, nullptr, nullptr);
    gn_finish<1><<<1, 256>>>();

    final_kernel<<<16384, 256>>>(x, g1_w, g1_b, lscale, out);

    (void)in_sizes; (void)n_in; (void)out_size;
}